// round 8
// baseline (speedup 1.0000x reference)
#include <cuda_runtime.h>

// SSIM over (32,3,512,512) fp32 pairs, 7x7 box window, interior crop, scalar mean.
// Separable box filter, all-scalar fp32. WARP-AUTONOMOUS TILES: warp w owns
// output cols [64w,64w+63], stages its own 36-pair (72-col) halo'd row segment
// into warp-private smem -> NO __syncthreads in the main loop, only __syncwarp
// per 2-row group. 2 columns/thread; col1 sums slid from col0. Fields per col:
// La, Lb, Q(=Saa+Sbb), P(=Sab); vertical 7-row sliding via register rings
// (compile-time slots, period 7). 182-row padded loop (13 x 14 rows); padded
// rows are clamped reads with emits masked. NSTRIP=3 -> 288 CTAs = one wave.
// Final reduction fused via last-block-done (fixed-order double sum).

#define W 512
#define H 512
#define NIMG 96            // 32 batch * 3 channels
#define NSTRIP 3
#define ROWS_OUT 169       // 3*169 = 507 >= 506 interior rows
#define NBLK (NIMG * NSTRIP)
#define NT 256             // 8 warps; warp w owns cols 64w..64w+63

__device__ float g_part[NBLK];
__device__ unsigned int g_count;   // zero-init; reset by last block each launch

__device__ __forceinline__ float frcp(float x) {
    float r; asm("rcp.approx.f32 %0, %1;" : "=f"(r) : "f"(x)); return r;
}

// Process one staged row from warp-private buffer BUFI, ring slot J
// (compile-time), row-in-strip index KK (emit masked to [6, klim]).
// Taps: buffer offsets l..l+4 hold pairs covering cols c0-4..c0+5.
#define PROC_ROW(BUFI, J, KK)                                                 \
do {                                                                          \
    const float4* wb = &sbuf[BUFI][w][l];                                     \
    const float4 s0 = wb[0];                                                  \
    const float4 s1 = wb[1];                                                  \
    const float4 s2 = wb[2];                                                  \
    const float4 s3 = wb[3];                                                  \
    const float4 s4 = wb[4];                                                  \
    const float a0 = s0.z, b0 = s0.w;                                         \
    const float a1 = s1.x, b1 = s1.y, a2 = s1.z, b2 = s1.w;                   \
    const float a3 = s2.x, b3 = s2.y, a4 = s2.z, b4 = s2.w;                   \
    const float a5 = s3.x, b5 = s3.y, a6 = s3.z, b6 = s3.w;                   \
    const float a7 = s4.x, b7 = s4.y;                                         \
    const float LA0 = ((a0 + a1) + (a2 + a3)) + ((a4 + a5) + a6);             \
    const float LB0 = ((b0 + b1) + (b2 + b3)) + ((b4 + b5) + b6);             \
    const float LA1 = (LA0 - a0) + a7;                                        \
    const float LB1 = (LB0 - b0) + b7;                                        \
    float Q0 = a0 * a0;                                                       \
    Q0 = fmaf(b0, b0, Q0);                                                    \
    Q0 = fmaf(a1, a1, Q0); Q0 = fmaf(b1, b1, Q0);                             \
    Q0 = fmaf(a2, a2, Q0); Q0 = fmaf(b2, b2, Q0);                             \
    Q0 = fmaf(a3, a3, Q0); Q0 = fmaf(b3, b3, Q0);                             \
    Q0 = fmaf(a4, a4, Q0); Q0 = fmaf(b4, b4, Q0);                             \
    Q0 = fmaf(a5, a5, Q0); Q0 = fmaf(b5, b5, Q0);                             \
    Q0 = fmaf(a6, a6, Q0); Q0 = fmaf(b6, b6, Q0);                             \
    float Q1 = fmaf(a7, a7, Q0);                                              \
    Q1 = fmaf(a0, -a0, Q1);                                                   \
    Q1 = fmaf(b7, b7, Q1);                                                    \
    Q1 = fmaf(b0, -b0, Q1);                                                   \
    const float pr0 = a0 * b0;                                                \
    float P0 = pr0;                                                           \
    P0 = fmaf(a1, b1, P0); P0 = fmaf(a2, b2, P0); P0 = fmaf(a3, b3, P0);      \
    P0 = fmaf(a4, b4, P0); P0 = fmaf(a5, b5, P0); P0 = fmaf(a6, b6, P0);      \
    const float P1 = fmaf(a7, b7, P0 - pr0);                                  \
    vA0 += LA0 - rA0[J];  rA0[J] = LA0;                                       \
    vB0 += LB0 - rB0[J];  rB0[J] = LB0;                                       \
    vQ0 += Q0  - rQ0[J];  rQ0[J] = Q0;                                        \
    vP0 += P0  - rP0[J];  rP0[J] = P0;                                        \
    vA1 += LA1 - rA1[J];  rA1[J] = LA1;                                       \
    vB1 += LB1 - rB1[J];  rB1[J] = LB1;                                       \
    vQ1 += Q1  - rQ1[J];  rQ1[J] = Q1;                                        \
    vP1 += P1  - rP1[J];  rP1[J] = P1;                                        \
    {                                                                         \
        const bool yok = ((KK) >= 6) && ((KK) <= klim);                       \
        const float ux0 = vA0 * INV49, uy0 = vB0 * INV49;                     \
        const float tt0 = ux0 * uy0;                                          \
        const float A1v0 = fmaf(tt0, 2.0f, C1);                               \
        float A2v0 = fmaf(vP0, TWO_CN_49, C2);                                \
        A2v0 = fmaf(tt0, -TWO_CN, A2v0);                                      \
        const float q20 = fmaf(uy0, uy0, ux0 * ux0);                          \
        const float B1v0 = q20 + C1;                                          \
        float B2v0 = fmaf(vQ0, CN_49, C2);                                    \
        B2v0 = fmaf(q20, -CN, B2v0);                                          \
        const float N0 = A1v0 * A2v0;                                         \
        const float D0 = B1v0 * B2v0;                                         \
        const float ux1 = vA1 * INV49, uy1 = vB1 * INV49;                     \
        const float tt1 = ux1 * uy1;                                          \
        const float A1v1 = fmaf(tt1, 2.0f, C1);                               \
        float A2v1 = fmaf(vP1, TWO_CN_49, C2);                                \
        A2v1 = fmaf(tt1, -TWO_CN, A2v1);                                      \
        const float q21 = fmaf(uy1, uy1, ux1 * ux1);                          \
        const float B1v1 = q21 + C1;                                          \
        float B2v1 = fmaf(vQ1, CN_49, C2);                                    \
        B2v1 = fmaf(q21, -CN, B2v1);                                          \
        const float N1 = A1v1 * A2v1;                                         \
        const float D1 = B1v1 * B2v1;                                         \
        const float R = frcp(D0 * D1);                                        \
        const float S0 = N0 * D1 * R;                                         \
        const float S1 = N1 * D0 * R;                                         \
        acc += (ok0 && yok) ? S0 : 0.0f;                                      \
        acc += (ok1 && yok) ? S1 : 0.0f;                                      \
    }                                                                         \
} while (0)

__global__ void __launch_bounds__(NT, 2) ssim_main(const float* __restrict__ A,
                                                   const float* __restrict__ B,
                                                   float* __restrict__ out) {
    // NP=49, CONV_NORM=49/48, C1=1e-4, C2=9e-4 (folded)
    const float C1        = 1e-4f;
    const float C2        = 9e-4f;
    const float INV49     = 1.0f / 49.0f;
    const float CN        = 49.0f / 48.0f;
    const float TWO_CN    = 49.0f / 24.0f;
    const float CN_49     = 1.0f / 48.0f;    // CN/49
    const float TWO_CN_49 = 1.0f / 24.0f;    // 2*CN/49

    const int t     = threadIdx.x;
    const int l     = t & 31;          // lane
    const int w     = t >> 5;          // warp = column tile
    const int blk   = blockIdx.x;
    const int img   = blk % NIMG;
    const int strip = blk / NIMG;

    const size_t base = (size_t)img * (W * H);
    // Warp w needs pairs 32w-2 .. 32w+33 (cols 64w-4 .. 64w+67).
    // Lane l loads pair pm; lanes 0..3 also load extra pair pe.
    const int  pm    = min(max(32 * w - 2 + l, 0), 255);
    const int  pe    = min(32 * w + 30 + l, 255);
    const bool has_e = (l < 4);
    const float2* __restrict__ apm = (const float2*)(A + base) + pm;
    const float2* __restrict__ bpm = (const float2*)(B + base) + pm;
    const float2* __restrict__ ape = (const float2*)(A + base) + pe;
    const float2* __restrict__ bpe = (const float2*)(B + base) + pe;

    // Warp-private 4-row ring: [buffer][warp][pair-offset]
    __shared__ float4 sbuf[4][8][36];

    const int  c0  = 64 * w + 2 * l;               // this thread's even column
    const bool ok0 = (c0 >= 3) && (c0 <= 508);
    const bool ok1 = (c0 >= 2) && (c0 <= 507);     // col c0+1 in [3,508]

    const int rstart = strip * ROWS_OUT;           // 0 / 169 / 338
    // Last emitting k: strips 0,1 -> 174 (169 rows); strip 2 -> 173 (168).
    const int klim = (strip == 2) ? 173 : 174;

    // Vertical sliding state (per column): La, Lb, Q, P
    float vA0 = 0.f, vB0 = 0.f, vQ0 = 0.f, vP0 = 0.f;
    float vA1 = 0.f, vB1 = 0.f, vQ1 = 0.f, vP1 = 0.f;
    float rA0[7] = {0,0,0,0,0,0,0}, rB0[7] = {0,0,0,0,0,0,0};
    float rQ0[7] = {0,0,0,0,0,0,0}, rP0[7] = {0,0,0,0,0,0,0};
    float rA1[7] = {0,0,0,0,0,0,0}, rB1[7] = {0,0,0,0,0,0,0};
    float rQ1[7] = {0,0,0,0,0,0,0}, rP1[7] = {0,0,0,0,0,0,0};
    float acc = 0.0f;

    // Prefetch rows 0,1 (main + extra)
    float2 ra0m = __ldg(apm + (rstart + 0) * (W / 2));
    float2 rb0m = __ldg(bpm + (rstart + 0) * (W / 2));
    float2 ra1m = __ldg(apm + (rstart + 1) * (W / 2));
    float2 rb1m = __ldg(bpm + (rstart + 1) * (W / 2));
    float2 ra0e = make_float2(0.f, 0.f), rb0e = ra0e, ra1e = ra0e, rb1e = ra0e;
    if (has_e) {
        ra0e = __ldg(ape + (rstart + 0) * (W / 2));
        rb0e = __ldg(bpe + (rstart + 0) * (W / 2));
        ra1e = __ldg(ape + (rstart + 1) * (W / 2));
        rb1e = __ldg(bpe + (rstart + 1) * (W / 2));
    }

    int bufp = 0;   // buffer pair base: 0 or 2

    // 182 rows = 13 x (7 pairs). Ring slot = row%7 compile-time (14%7==0).
    // Rows 175..181 are clamped re-reads; emits beyond klim are masked.
    #pragma unroll 1
    for (int it = 0; it < 13; it++) {
        const int kb = it * 14;
        #pragma unroll
        for (int m = 0; m < 7; m++) {
            const int k0 = kb + 2 * m;

            sbuf[bufp    ][w][l] = make_float4(ra0m.x, rb0m.x, ra0m.y, rb0m.y);
            sbuf[bufp + 1][w][l] = make_float4(ra1m.x, rb1m.x, ra1m.y, rb1m.y);
            if (has_e) {
                sbuf[bufp    ][w][32 + l] = make_float4(ra0e.x, rb0e.x, ra0e.y, rb0e.y);
                sbuf[bufp + 1][w][32 + l] = make_float4(ra1e.x, rb1e.x, ra1e.y, rb1e.y);
            }

            const int rn0 = min(rstart + k0 + 2, H - 1) * (W / 2);
            const int rn1 = min(rstart + k0 + 3, H - 1) * (W / 2);
            ra0m = __ldg(apm + rn0);
            rb0m = __ldg(bpm + rn0);
            ra1m = __ldg(apm + rn1);
            rb1m = __ldg(bpm + rn1);
            if (has_e) {
                ra0e = __ldg(ape + rn0);
                rb0e = __ldg(bpe + rn0);
                ra1e = __ldg(ape + rn1);
                rb1e = __ldg(bpe + rn1);
            }

            __syncwarp();                 // warp-local: no cross-warp coupling

            PROC_ROW(bufp,     (2 * m) % 7,     k0);
            PROC_ROW(bufp + 1, (2 * m + 1) % 7, k0 + 1);

            bufp ^= 2;
        }
    }

    // Deterministic block reduction
    #pragma unroll
    for (int o = 16; o > 0; o >>= 1)
        acc += __shfl_xor_sync(0xFFFFFFFFu, acc, o);

    __shared__ float wsum[8];
    __shared__ bool  is_last;
    if (l == 0) wsum[w] = acc;
    __syncthreads();
    if (t == 0) {
        float v = wsum[0] + wsum[1] + wsum[2] + wsum[3]
                + wsum[4] + wsum[5] + wsum[6] + wsum[7];
        g_part[blk] = v;
        __threadfence();
        unsigned int prev = atomicAdd(&g_count, 1u);
        is_last = (prev == NBLK - 1);
    }
    __syncthreads();

    // Last finished CTA: fixed-order double-precision final sum (deterministic)
    if (is_last) {
        double s = 0.0;
        for (int i = t; i < NBLK; i += NT) s += (double)__ldcg(&g_part[i]);
        __shared__ double sd[NT];
        sd[t] = s;
        __syncthreads();
        #pragma unroll
        for (int st = NT / 2; st > 0; st >>= 1) {
            if (t < st) sd[t] += sd[t + st];
            __syncthreads();
        }
        if (t == 0) {
            out[0] = (float)(sd[0] * (1.0 / ((double)NIMG * 506.0 * 506.0)));
            g_count = 0;   // reset for next graph replay
        }
    }
}

extern "C" void kernel_launch(void* const* d_in, const int* in_sizes, int n_in,
                              void* d_out, int out_size) {
    const float* img1 = (const float*)d_in[0];
    const float* img2 = (const float*)d_in[1];
    float* out = (float*)d_out;
    (void)in_sizes; (void)n_in; (void)out_size;

    ssim_main<<<NBLK, NT>>>(img1, img2, out);
}